// round 2
// baseline (speedup 1.0000x reference)
#include <cuda_runtime.h>
#include <math.h>

#define NSTEP 100
#define B_TOTAL 2048
#define WARPS_PER_CTA 8
#define THREADS 256
#define NCTAS (B_TOTAL / WARPS_PER_CTA)

// Shared layout (floats):
//  w2s   : 13312   (w2 transposed to [c][ky][kx][oc], oc contiguous)
//  wfP4  : 1152    (288 float4: per (p,lane): wf0/wf1 for oc=2l and 2l+1)
//  dec   : 468 u32 (per layer-1 element: (w2 byte offset)<<9 | 9-bit validity mask)
//  w1s   : 208
//  b1s   : 16
//  cur1s : 8*480   (per-warp constant input current, zero-padded)
//  xs    : 8*256   (per-warp input image scratch, prologue only)
#define SMEM_FLOATS (13312 + 1152 + 468 + 208 + 16 + 8*480 + 8*256)

__global__ __launch_bounds__(THREADS, 2) void snn_kernel(
    const float* __restrict__ x,  const float* __restrict__ w1, const float* __restrict__ b1,
    const float* __restrict__ w2, const float* __restrict__ b2, const float* __restrict__ wf,
    const float* __restrict__ bf, float* __restrict__ out)
{
    extern __shared__ float smem[];
    float*    w2s  = smem;                                   // 13312
    float4*   wfP4 = (float4*)(smem + 13312);                // 288 f4
    unsigned* dec  = (unsigned*)(smem + 13312 + 1152);       // 468
    float*    w1s  = (float*)(dec + 468);                    // 208
    float*    b1s  = w1s + 208;                              // 16
    float*    cur1s= b1s + 16;                               // 8*480
    float*    xs   = cur1s + 8*480;                          // 8*256

    const int tid  = threadIdx.x;
    const int wid  = tid >> 5;
    const int lane = tid & 31;
    const int b    = blockIdx.x * WARPS_PER_CTA + wid;

    // ---- prologue: stage weights / tables ----
    for (int idx = tid; idx < 13312; idx += THREADS) {       // w2[oc][c*16+kk] -> w2s[(c*16+kk)*64+oc]
        int oc = idx / 208; int r = idx - oc * 208;
        w2s[r * 64 + oc] = w2[idx];
    }
    for (int idx = tid; idx < 288; idx += THREADS) {         // wf permute: idx = p*32 + l
        int p = idx >> 5, l = idx & 31;
        int i0 = (2 * l) * 9 + p, i1 = (2 * l + 1) * 9 + p;
        wfP4[idx] = make_float4(wf[i0], wf[576 + i0], wf[i1], wf[576 + i1]);
    }
    for (int e = tid; e < 468; e += THREADS) {               // decode LUT for sparse conv2
        int c = e / 36, r = e - c * 36, iy = r / 6, ix = r - iy * 6;
        int s0 = iy * 4 + ix;
        unsigned vm = 0;
        for (int oy = 0; oy < 3; oy++)
            for (int ox = 0; ox < 3; ox++) {
                int ky = iy - oy, kx = ix - ox;
                if (ky >= 0 && ky < 4 && kx >= 0 && kx < 4) vm |= 1u << (oy * 3 + ox);
            }
        dec[e] = ((unsigned)(c * 4096 + s0 * 256) << 9) | vm;
    }
    if (tid < 208) w1s[tid] = w1[tid];
    if (tid < 13)  b1s[tid] = b1[tid];
    __syncthreads();

    // ---- prologue per warp: load x, compute cur1 = maxpool2(conv1(x)+b1) ----
    {
        float4* xs4 = (float4*)(xs + wid * 256);
        const float4* xg = (const float4*)(x + (size_t)b * 256);
        xs4[lane] = xg[lane];
        xs4[lane + 32] = xg[lane + 32];
        __syncwarp();
        const float* xw = xs + wid * 256;
        float* cw = cur1s + wid * 480;
        #pragma unroll
        for (int k = 0; k < 15; k++) {
            int e = k * 32 + lane;
            float val = 0.f;
            if (e < 468) {
                int c = e / 36, r = e - c * 36, py = r / 6, px = r - py * 6;
                float m = -INFINITY;
                #pragma unroll
                for (int dy = 0; dy < 2; dy++)
                #pragma unroll
                for (int dx = 0; dx < 2; dx++) {
                    int iy0 = 2 * py + dy, ix0 = 2 * px + dx;
                    float s = 0.f;
                    #pragma unroll
                    for (int ky = 0; ky < 4; ky++)
                    #pragma unroll
                    for (int kx = 0; kx < 4; kx++)
                        s = fmaf(xw[(iy0 + ky) * 16 + ix0 + kx], w1s[c * 16 + ky * 4 + kx], s);
                    s = __fadd_rn(s, b1s[c]);
                    m = fmaxf(m, s);
                }
                val = m;
            }
            cw[k * 32 + lane] = val;   // zero-pad e in [468,480)
        }
    }

    // ---- recurrent state in registers ----
    float v1[15], i1[15];
    #pragma unroll
    for (int k = 0; k < 15; k++) { v1[k] = 0.f; i1[k] = 0.f; }
    float2 b2p = ((const float2*)b2)[lane];     // oc = 2*lane, 2*lane+1
    float2 acc[9], v2[9], i2[9];
    #pragma unroll
    for (int p = 0; p < 9; p++) {
        acc[p] = b2p;
        v2[p] = make_float2(0.f, 0.f);
        i2[p] = make_float2(0.f, 0.f);
    }
    float v30 = 0.f, i30 = 0.f, v31 = 0.f, i31 = 0.f, s0 = 0.f, s1 = 0.f;
    const float bf0 = bf[0], bf1 = bf[1];
    const char* w2bytes = (const char*)w2s + lane * 8;
    const float* cw = cur1s + wid * 480;
    float2* outv = (float2*)(out + 2 * B_TOTAL) + b;

    // ---- 100 timesteps ----
    for (int t = 0; t < NSTEP; t++) {
        // layer 1 LIF + sparse conv2 accumulation
        #pragma unroll
        for (int k = 0; k < 15; k++) {
            float cur = cw[k * 32 + lane];
            float vd = __fadd_rn(v1[k], __fmul_rn(0.1f, __fsub_rn(i1[k], v1[k])));
            bool z = vd > 1.0f;
            v1[k] = z ? 0.f : vd;
            i1[k] = __fadd_rn(__fmul_rn(0.8f, i1[k]), cur);
            unsigned m = __ballot_sync(0xffffffffu, z);
            while (m) {
                int j = __ffs(m) - 1;
                m &= m - 1;
                unsigned d = dec[k * 32 + j];
                const char* base = w2bytes + (d >> 9);
                unsigned vm = d & 511u;
                #pragma unroll
                for (int p = 0; p < 9; p++) {
                    const int cpos = (p / 3) * 4 + (p % 3);
                    if (vm & (1u << p)) {
                        float2 wv = *(const float2*)(base - cpos * 256);
                        acc[p].x = __fadd_rn(acc[p].x, wv.x);
                        acc[p].y = __fadd_rn(acc[p].y, wv.y);
                    }
                }
            }
        }

        // layer 2 LIF + sparse FC accumulation
        float c30 = 0.f, c31 = 0.f;
        #pragma unroll
        for (int p = 0; p < 9; p++) {
            float vdx = __fadd_rn(v2[p].x, __fmul_rn(0.1f, __fsub_rn(i2[p].x, v2[p].x)));
            float vdy = __fadd_rn(v2[p].y, __fmul_rn(0.1f, __fsub_rn(i2[p].y, v2[p].y)));
            bool zx = vdx > 1.0f, zy = vdy > 1.0f;
            v2[p].x = zx ? 0.f : vdx;
            v2[p].y = zy ? 0.f : vdy;
            i2[p].x = __fadd_rn(__fmul_rn(0.8f, i2[p].x), acc[p].x);
            i2[p].y = __fadd_rn(__fmul_rn(0.8f, i2[p].y), acc[p].y);
            acc[p] = b2p;
            if (zx || zy) {
                float4 q = wfP4[p * 32 + lane];
                if (zx) { c30 = __fadd_rn(c30, q.x); c31 = __fadd_rn(c31, q.y); }
                if (zy) { c30 = __fadd_rn(c30, q.z); c31 = __fadd_rn(c31, q.w); }
            }
        }
        #pragma unroll
        for (int o = 16; o > 0; o >>= 1) {
            c30 += __shfl_xor_sync(0xffffffffu, c30, o);
            c31 += __shfl_xor_sync(0xffffffffu, c31, o);
        }
        float cur30 = __fadd_rn(c30, bf0);
        float cur31 = __fadd_rn(c31, bf1);

        // layer 3 LIF (redundant across lanes; lane 0 records)
        float vd0 = __fadd_rn(v30, __fmul_rn(0.1f, __fsub_rn(i30, v30)));
        float vd1 = __fadd_rn(v31, __fmul_rn(0.1f, __fsub_rn(i31, v31)));
        bool z0 = vd0 > 1.0f, z1 = vd1 > 1.0f;
        v30 = z0 ? 0.f : vd0;
        v31 = z1 ? 0.f : vd1;
        i30 = __fadd_rn(__fmul_rn(0.8f, i30), cur30);
        i31 = __fadd_rn(__fmul_rn(0.8f, i31), cur31);
        s0 += z0 ? 1.f : 0.f;
        s1 += z1 ? 1.f : 0.f;
        if (lane == 0) outv[t * B_TOTAL] = make_float2(v30, v31);
    }
    if (lane == 0) ((float2*)out)[b] = make_float2(s0, s1);
}

extern "C" void kernel_launch(void* const* d_in, const int* in_sizes, int n_in,
                              void* d_out, int out_size) {
    const float* x  = (const float*)d_in[0];
    const float* w1 = (const float*)d_in[1];
    const float* b1 = (const float*)d_in[2];
    const float* w2 = (const float*)d_in[3];
    const float* b2 = (const float*)d_in[4];
    const float* wf = (const float*)d_in[5];
    const float* bf = (const float*)d_in[6];
    float* out = (float*)d_out;

    size_t shmem = (size_t)SMEM_FLOATS * sizeof(float);
    cudaFuncSetAttribute(snn_kernel, cudaFuncAttributeMaxDynamicSharedMemorySize, (int)shmem);
    snn_kernel<<<NCTAS, THREADS, shmem>>>(x, w1, b1, w2, b2, wf, bf, out);
}